// round 1
// baseline (speedup 1.0000x reference)
#include <cuda_runtime.h>
#include <cuda_fp16.h>
#include <math.h>

#define NHID 1024
#define NLAY 4
#define NST  64
#define TSTEPS 101
#define GROWS 4096                       // 4*NHID gate rows per layer
#define WSZ (NLAY*GROWS*NHID)            // 16,777,216 weights per matrix set

#define OUT_STATES 0
#define OUT_PROBS (TSTEPS*NST)           // 6464
#define OUT_SAMP  (OUT_PROBS + TSTEPS*2) // 6666

// ---- persistent scratch (device globals; no allocation allowed) ----
__device__ __half g_wih[WSZ];            // fp16 input weights  (32 MB)
__device__ __half g_whh[WSZ];            // fp16 hidden weights (32 MB)
__device__ float  g_bias[NLAY*GROWS];    // bih + bhh
__device__ __half g_ws[NST*NHID];        // fp16 state head
__device__ float  g_h[2][NLAY][NHID];    // double-buffered hidden
__device__ float  g_c[NLAY][NHID];       // cell state (per-unit owner, no race)
__device__ unsigned g_arrive;
__device__ volatile unsigned g_phase;

// ---- prep: fp32 -> fp16 weight conversion (pure bandwidth, ~25us) ----
__global__ void k_prep(const float* __restrict__ wih, const float* __restrict__ whh) {
    int i = (blockIdx.x * blockDim.x + threadIdx.x) * 4;
    if (i >= WSZ) return;
    float4 a = *(const float4*)(wih + i);
    __half2* d = (__half2*)(g_wih + i);
    d[0] = __floats2half2_rn(a.x, a.y);
    d[1] = __floats2half2_rn(a.z, a.w);
    float4 b = *(const float4*)(whh + i);
    __half2* e = (__half2*)(g_whh + i);
    e[0] = __floats2half2_rn(b.x, b.y);
    e[1] = __floats2half2_rn(b.z, b.w);
}

// ---- init: biases, head weights, state zeroing, barrier reset, fixed outputs ----
__global__ void k_init(const float* __restrict__ bih, const float* __restrict__ bhh,
                       const float* __restrict__ ws, float* __restrict__ dout) {
    int i = blockIdx.x * blockDim.x + threadIdx.x;
    if (i < NLAY*GROWS)  g_bias[i] = bih[i] + bhh[i];
    if (i < NST*NHID)    g_ws[i] = __float2half_rn(ws[i]);
    if (i < 2*NLAY*NHID) ((float*)g_h)[i] = 0.f;
    if (i < NLAY*NHID)   ((float*)g_c)[i] = 0.f;
    if (i < TSTEPS)      dout[OUT_SAMP + i] = (i == TSTEPS-1) ? 1.f : 0.f;
    if (i == 0) {
        g_arrive = 0;
        g_phase = 0;
        dout[OUT_PROBS + 2*(TSTEPS-1) + 0] = 0.f;  // forced last-step probs
        dout[OUT_PROBS + 2*(TSTEPS-1) + 1] = 1.f;
    }
}

// ---- helpers ----
__device__ __forceinline__ float dot8(uint4 w, float4 a, float4 b) {
    float2 p0 = __half22float2(*(const __half2*)&w.x);
    float2 p1 = __half22float2(*(const __half2*)&w.y);
    float2 p2 = __half22float2(*(const __half2*)&w.z);
    float2 p3 = __half22float2(*(const __half2*)&w.w);
    return p0.x*a.x + p0.y*a.y + p1.x*a.z + p1.y*a.w
         + p2.x*b.x + p2.y*b.y + p3.x*b.z + p3.y*b.w;
}

__device__ __forceinline__ float wredsum(float v) {
    v += __shfl_xor_sync(0xffffffffu, v, 16);
    v += __shfl_xor_sync(0xffffffffu, v, 8);
    v += __shfl_xor_sync(0xffffffffu, v, 4);
    v += __shfl_xor_sync(0xffffffffu, v, 2);
    v += __shfl_xor_sync(0xffffffffu, v, 1);
    return v;
}

__device__ __forceinline__ float sigf(float x) { return 1.f / (1.f + expf(-x)); }

// software grid barrier (all CTAs co-resident: grid = 148 <= SM count, 1 CTA/SM)
__device__ __forceinline__ void gbar() {
    __syncthreads();
    if (threadIdx.x == 0) {
        unsigned ph = g_phase;
        __threadfence();
        unsigned prev = atomicAdd(&g_arrive, 1u);
        if (prev == gridDim.x - 1) {
            g_arrive = 0;
            __threadfence();
            g_phase = ph + 1;
        } else {
            while (g_phase == ph) { }
            __threadfence();
        }
    }
    __syncthreads();
}

// ---- main persistent kernel: 404 layer-step phases ----
__global__ void __launch_bounds__(448, 1) k_lstm(
    const float* __restrict__ z,
    const float* __restrict__ bs,
    const float* __restrict__ wp,
    const float* __restrict__ bp,
    float* __restrict__ dout)
{
    __shared__ float s_inp[NHID];
    __shared__ float s_h[NHID];
    __shared__ float s_red[7][2][4];

    const int bid  = blockIdx.x;
    const int tid  = threadIdx.x;
    const int wid  = tid >> 5;
    const int lane = tid & 31;
    const bool is_head = (bid == (int)gridDim.x - 1);

    for (int t = 0; t < TSTEPS; ++t) {
        const int wb = t & 1;      // write buffer for this step's h
        const int rb = wb ^ 1;     // previous step's h
        for (int l = 0; l < NLAY; ++l) {
            if (!is_head) {
                const bool use_ih = (l > 0) || (t == 0);   // layer-0 input is 0 for t>0
                const float* hsrc = g_h[rb][l];
                const float* isrc = (l == 0) ? z : g_h[wb][l-1];
                for (int i = tid; i < NHID; i += 448) {
                    s_h[i] = hsrc[i];
                    if (use_ih) s_inp[i] = isrc[i];
                }
                __syncthreads();

                const int jl = wid >> 1;       // local unit 0..6
                const int hf = wid & 1;        // K-half
                const int j  = bid * 7 + jl;
                if (j < NHID) {
                    const int kb = hf * 512;
                    float acc[4];
                    #pragma unroll
                    for (int g = 0; g < 4; ++g) {
                        const int row = l * GROWS + g * NHID + j;
                        const __half* rih = g_wih + (size_t)row * NHID + kb;
                        const __half* rhh = g_whh + (size_t)row * NHID + kb;
                        float a = 0.f;
                        #pragma unroll
                        for (int it = 0; it < 2; ++it) {
                            const int k = it * 256 + lane * 8;
                            uint4 whv = *(const uint4*)(rhh + k);
                            float4 h0 = *(const float4*)(s_h + kb + k);
                            float4 h1 = *(const float4*)(s_h + kb + k + 4);
                            a += dot8(whv, h0, h1);
                            if (use_ih) {
                                uint4 wiv = *(const uint4*)(rih + k);
                                float4 x0 = *(const float4*)(s_inp + kb + k);
                                float4 x1 = *(const float4*)(s_inp + kb + k + 4);
                                a += dot8(wiv, x0, x1);
                            }
                        }
                        acc[g] = wredsum(a);
                    }
                    if (lane == 0) {
                        s_red[jl][hf][0] = acc[0];
                        s_red[jl][hf][1] = acc[1];
                        s_red[jl][hf][2] = acc[2];
                        s_red[jl][hf][3] = acc[3];
                    }
                }
                __syncthreads();
                if (tid < 7) {
                    const int jj = bid * 7 + tid;
                    if (jj < NHID) {
                        const float* bl = g_bias + l * GROWS;
                        float gi = s_red[tid][0][0] + s_red[tid][1][0] + bl[jj];
                        float gf = s_red[tid][0][1] + s_red[tid][1][1] + bl[NHID   + jj];
                        float gg = s_red[tid][0][2] + s_red[tid][1][2] + bl[2*NHID + jj];
                        float go = s_red[tid][0][3] + s_red[tid][1][3] + bl[3*NHID + jj];
                        float cn = sigf(gf) * g_c[l][jj] + sigf(gi) * tanhf(gg);
                        float hn = sigf(go) * tanhf(cn);
                        g_c[l][jj] = cn;
                        g_h[wb][l][jj] = hn;
                    }
                }
            } else if (t >= 1) {
                // head CTA: heads for step t-1, spread over the 4 phases of step t.
                // g_h[rb][3] == h3(t-1); phase (t,3) writes g_h[wb][3] (other buffer).
                const float* o = g_h[rb][3];
                for (int i = tid; i < NHID; i += 448) s_inp[i] = o[i];
                __syncthreads();
                const int cs = l * 17;
                const int ce = (cs + 17 < 66) ? cs + 17 : 66;
                for (int r = cs + wid; r < ce; r += 14) {
                    if (r < NST) {
                        const __half* row = g_ws + (size_t)r * NHID;
                        float a = 0.f;
                        #pragma unroll
                        for (int it = 0; it < 4; ++it) {
                            const int k = it * 256 + lane * 8;
                            uint4 wv  = *(const uint4*)(row + k);
                            float4 x0 = *(const float4*)(s_inp + k);
                            float4 x1 = *(const float4*)(s_inp + k + 4);
                            a += dot8(wv, x0, x1);
                        }
                        a = wredsum(a);
                        if (lane == 0) dout[OUT_STATES + (t-1) * NST + r] = a + bs[r];
                    } else if (r == NST) {
                        float a0 = 0.f, a1 = 0.f;
                        #pragma unroll
                        for (int it = 0; it < 4; ++it) {
                            const int k = it * 256 + lane * 8;
                            float4 x0  = *(const float4*)(s_inp + k);
                            float4 x1  = *(const float4*)(s_inp + k + 4);
                            float4 w00 = *(const float4*)(wp + k);
                            float4 w01 = *(const float4*)(wp + k + 4);
                            float4 w10 = *(const float4*)(wp + NHID + k);
                            float4 w11 = *(const float4*)(wp + NHID + k + 4);
                            a0 += w00.x*x0.x + w00.y*x0.y + w00.z*x0.z + w00.w*x0.w
                                + w01.x*x1.x + w01.y*x1.y + w01.z*x1.z + w01.w*x1.w;
                            a1 += w10.x*x0.x + w10.y*x0.y + w10.z*x0.z + w10.w*x0.w
                                + w11.x*x1.x + w11.y*x1.y + w11.z*x1.z + w11.w*x1.w;
                        }
                        a0 = wredsum(a0); a1 = wredsum(a1);
                        if (lane == 0) {
                            float l0 = a0 + bp[0] + 1.0f;   // P_BIAS on logit 0
                            float l1 = a1 + bp[1];
                            float m  = fmaxf(l0, l1);
                            float e0 = expf(l0 - m), e1 = expf(l1 - m);
                            float inv = 1.f / (e0 + e1);
                            dout[OUT_PROBS + (t-1)*2 + 0] = e0 * inv;
                            dout[OUT_PROBS + (t-1)*2 + 1] = e1 * inv;
                        }
                    }
                }
            }
            gbar();
        }
    }

    // epilogue: heads for the final step (t = 100). probs/samples already fixed by k_init.
    if (is_head) {
        const float* o = g_h[(TSTEPS-1) & 1][3];
        for (int i = tid; i < NHID; i += 448) s_inp[i] = o[i];
        __syncthreads();
        for (int r = wid; r < NST; r += 14) {
            const __half* row = g_ws + (size_t)r * NHID;
            float a = 0.f;
            #pragma unroll
            for (int it = 0; it < 4; ++it) {
                const int k = it * 256 + lane * 8;
                uint4 wv  = *(const uint4*)(row + k);
                float4 x0 = *(const float4*)(s_inp + k);
                float4 x1 = *(const float4*)(s_inp + k + 4);
                a += dot8(wv, x0, x1);
            }
            a = wredsum(a);
            if (lane == 0) dout[OUT_STATES + (TSTEPS-1) * NST + r] = a + bs[r];
        }
    }
}

extern "C" void kernel_launch(void* const* d_in, const int* in_sizes, int n_in,
                              void* d_out, int out_size) {
    (void)in_sizes; (void)n_in; (void)out_size;
    const float* z   = (const float*)d_in[0];
    const float* wih = (const float*)d_in[1];
    const float* whh = (const float*)d_in[2];
    const float* bih = (const float*)d_in[3];
    const float* bhh = (const float*)d_in[4];
    const float* ws  = (const float*)d_in[5];
    const float* bs  = (const float*)d_in[6];
    const float* wp  = (const float*)d_in[7];
    const float* bp  = (const float*)d_in[8];
    float* out = (float*)d_out;

    k_prep<<<WSZ / 4 / 256, 256>>>(wih, whh);
    k_init<<<256, 256>>>(bih, bhh, ws, out);
    k_lstm<<<148, 448>>>(z, bs, wp, bp, out);
}

// round 2
// speedup vs baseline: 2.5564x; 2.5564x over previous
#include <cuda_runtime.h>
#include <cuda_fp16.h>
#include <math.h>

#define NHID   1024
#define NLAY   4
#define NST    64
#define TSTEPS 101
#define NUNITS (NLAY*NHID)            // 4096
#define ROWLEN 2048                   // packed row: [Whh(1024) | Wih(1024)]
#define NROWS  (NUNITS*4)             // 16384 gate rows
#define NPHASE (TSTEPS + NLAY - 1)    // 104 wavefront phases
#define NCTA     148
#define NWORK    147
#define NTHREADS 896                  // 28 warps

#define OUT_STATES 0
#define OUT_PROBS  (TSTEPS*NST)              // 6464
#define OUT_SAMP   (OUT_PROBS + TSTEPS*2)    // 6666

// ---- persistent device state (no allocation allowed) ----
__device__ __align__(128) __half g_wpack[(size_t)NROWS * ROWLEN];  // 64 MB packed fp16 weights
__device__ float  g_bias[NLAY*4*NHID];                             // bih + bhh
__device__ __align__(16) __half g_ws[NST*NHID];                    // fp16 state head
__device__ __align__(16) __half g_hout[2][NLAY][NHID];             // double-buffered hidden (fp16)
__device__ unsigned g_arrive;                                      // monotonic barrier counter

// ---- prep: pack [Whh|Wih] per (unit,gate) row, fp32->fp16 ----
__global__ void k_prep(const float* __restrict__ wih, const float* __restrict__ whh) {
    int row = blockIdx.x;                 // 0..16383 == u*4+g
    int u = row >> 2, g = row & 3;
    int l = u >> 10, j = u & 1023;
    size_t src = ((size_t)l*4096 + g*1024 + j) * 1024;
    __half* dst = g_wpack + (size_t)row * ROWLEN;
    int k = threadIdx.x * 4;              // 256 threads x 4 = 1024
    float4 hv = *(const float4*)(whh + src + k);
    __half2* d0 = (__half2*)(dst + k);
    d0[0] = __floats2half2_rn(hv.x, hv.y);
    d0[1] = __floats2half2_rn(hv.z, hv.w);
    float4 iv = *(const float4*)(wih + src + k);
    __half2* d1 = (__half2*)(dst + 1024 + k);
    d1[0] = __floats2half2_rn(iv.x, iv.y);
    d1[1] = __floats2half2_rn(iv.z, iv.w);
}

// ---- init: biases, head weights, h buffers, barrier, fixed outputs ----
__global__ void k_init(const float* __restrict__ bih, const float* __restrict__ bhh,
                       const float* __restrict__ ws, float* __restrict__ dout) {
    int i = blockIdx.x * blockDim.x + threadIdx.x;     // 65536 threads
    if (i < NLAY*4*NHID)  g_bias[i] = bih[i] + bhh[i];
    if (i < NST*NHID)     g_ws[i] = __float2half_rn(ws[i]);
    if (i < 2*NLAY*NHID)  ((__half*)g_hout)[i] = __float2half(0.f);
    if (i < TSTEPS)       dout[OUT_SAMP + i] = (i == TSTEPS-1) ? 1.f : 0.f;
    if (i == 0) {
        g_arrive = 0;
        dout[OUT_PROBS + 2*(TSTEPS-1) + 0] = 0.f;   // forced last-step probs
        dout[OUT_PROBS + 2*(TSTEPS-1) + 1] = 1.f;
    }
}

// ---- helpers ----
__device__ __forceinline__ float d8w(uint4 w, float2 x0, float2 x1, float2 x2, float2 x3) {
    float2 w0 = __half22float2(((const __half2*)&w)[0]);
    float2 w1 = __half22float2(((const __half2*)&w)[1]);
    float2 w2 = __half22float2(((const __half2*)&w)[2]);
    float2 w3 = __half22float2(((const __half2*)&w)[3]);
    return w0.x*x0.x + w0.y*x0.y + w1.x*x1.x + w1.y*x1.y
         + w2.x*x2.x + w2.y*x2.y + w3.x*x3.x + w3.y*x3.y;
}

__device__ __forceinline__ float d8hh(uint4 w, uint4 x) {
    float2 x0 = __half22float2(((const __half2*)&x)[0]);
    float2 x1 = __half22float2(((const __half2*)&x)[1]);
    float2 x2 = __half22float2(((const __half2*)&x)[2]);
    float2 x3 = __half22float2(((const __half2*)&x)[3]);
    return d8w(w, x0, x1, x2, x3);
}

__device__ __forceinline__ float wredsum(float v) {
    v += __shfl_xor_sync(0xffffffffu, v, 16);
    v += __shfl_xor_sync(0xffffffffu, v, 8);
    v += __shfl_xor_sync(0xffffffffu, v, 4);
    v += __shfl_xor_sync(0xffffffffu, v, 2);
    v += __shfl_xor_sync(0xffffffffu, v, 1);
    return v;
}

__device__ __forceinline__ float sigf(float x) { return 1.f / (1.f + __expf(-x)); }

// 4 gate-row dot products over NC*256 elements (x shared across gates from smem fp16)
template <int NC>
__device__ __forceinline__ void matrow(const __half* wr, const __half* sx, int lane,
                                       float& a0, float& a1, float& a2, float& a3) {
    const uint4* xs  = (const uint4*)sx;
    const uint4* wp4 = (const uint4*)wr;
#pragma unroll
    for (int cch = 0; cch < NC; ++cch) {
        uint4 xv = xs[cch*32 + lane];
        float2 x0 = __half22float2(((const __half2*)&xv)[0]);
        float2 x1 = __half22float2(((const __half2*)&xv)[1]);
        float2 x2 = __half22float2(((const __half2*)&xv)[2]);
        float2 x3 = __half22float2(((const __half2*)&xv)[3]);
        uint4 w0 = wp4[cch*32 + lane];
        uint4 w1 = wp4[cch*32 + lane + 256];
        uint4 w2 = wp4[cch*32 + lane + 512];
        uint4 w3 = wp4[cch*32 + lane + 768];
        a0 += d8w(w0, x0, x1, x2, x3);
        a1 += d8w(w1, x0, x1, x2, x3);
        a2 += d8w(w2, x0, x1, x2, x3);
        a3 += d8w(w3, x0, x1, x2, x3);
    }
}

// grid barrier: monotonic counter, release-add + acquire-poll
__device__ __forceinline__ void gbar(unsigned target) {
    __syncthreads();
    if (threadIdx.x == 0) {
        asm volatile("red.release.gpu.global.add.u32 [%0], %1;"
                     :: "l"(&g_arrive), "r"(1u) : "memory");
        unsigned v;
        do {
            asm volatile("ld.acquire.gpu.global.u32 %0, [%1];"
                         : "=r"(v) : "l"(&g_arrive) : "memory");
        } while (v < target);
    }
    __syncthreads();
}

// ---- main persistent kernel: 104 wavefront phases ----
__global__ void __launch_bounds__(NTHREADS, 1) k_lstm(
    const float* __restrict__ z,
    const float* __restrict__ bs,
    const float* __restrict__ wp,
    const float* __restrict__ bp,
    float* __restrict__ dout)
{
    __shared__ __align__(16) __half s_x[NLAY * ROWLEN];   // per-layer [h_l(t-1) | x_l(t)]

    const int tid  = threadIdx.x;
    const int bid  = blockIdx.x;
    const int wid  = tid >> 5;
    const int lane = tid & 31;
    const bool is_head = (bid == NCTA - 1);

    int u = is_head ? -1 : (wid * NWORK + bid);     // permanent unit ownership
    if (u >= NUNITS) u = -1;
    const int l = (u >= 0) ? (u >> 10) : 0;
    const int j = (u >= 0) ? (u & 1023) : 0;
    const __half* wr = g_wpack + (size_t)((u >= 0) ? u : 0) * 4 * ROWLEN;

    float c = 0.f;                                  // cell state lives in registers

    for (int p = 0; p < NPHASE; ++p) {
        const int rb = (p & 1) ^ 1;                 // previous-phase buffer
        const int wbuf = p & 1;

        // stage activations into smem as fp16: s_x[l] = [g_hout[rb][l] | input_l]
        for (int idx = tid; idx < NLAY*ROWLEN; idx += NTHREADS) {
            int ll = idx >> 11, k = idx & 2047;
            __half v;
            if (k < NHID)      v = g_hout[rb][ll][k];
            else if (ll > 0)   v = g_hout[rb][ll-1][k - NHID];
            else               v = (p == 0) ? __float2half_rn(z[k - NHID]) : __float2half(0.f);
            s_x[idx] = v;
        }
        __syncthreads();

        if (u >= 0) {
            const int t = p - l;
            if (t >= 0 && t < TSTEPS) {
                float a0 = 0.f, a1 = 0.f, a2 = 0.f, a3 = 0.f;
                if (l == 0 && p > 0)
                    matrow<4>(wr, s_x, lane, a0, a1, a2, a3);      // x==0: Whh half only
                else
                    matrow<8>(wr, s_x + l*ROWLEN, lane, a0, a1, a2, a3);
                a0 = wredsum(a0); a1 = wredsum(a1);
                a2 = wredsum(a2); a3 = wredsum(a3);
                const float* bl = g_bias + l*4096 + j;
                float gi = a0 + bl[0];
                float gf = a1 + bl[1024];
                float gg = a2 + bl[2048];
                float go = a3 + bl[3072];
                c = sigf(gf) * c + sigf(gi) * tanhf(gg);
                float hn = sigf(go) * tanhf(c);
                if (lane == 0) g_hout[wbuf][l][j] = __float2half_rn(hn);
            }
        } else if (is_head && p >= 4) {
            // heads for t = p-4; h_3(t) == g_hout[rb][3] == s_x[3*ROWLEN..+1024)
            const int t = p - 4;
            const uint4* xs = (const uint4*)(s_x + 3*ROWLEN);
            for (int r = wid; r < NST + 2; r += 28) {
                if (r < NST) {
                    const uint4* wrow = (const uint4*)(g_ws + r*NHID);
                    float a = 0.f;
#pragma unroll
                    for (int cch = 0; cch < 4; ++cch)
                        a += d8hh(wrow[cch*32 + lane], xs[cch*32 + lane]);
                    a = wredsum(a);
                    if (lane == 0) dout[OUT_STATES + t*NST + r] = a + bs[r];
                } else if (r == NST) {
                    float a0 = 0.f, a1 = 0.f;
#pragma unroll
                    for (int cch = 0; cch < 4; ++cch) {
                        uint4 xv = xs[cch*32 + lane];
                        float2 x0 = __half22float2(((const __half2*)&xv)[0]);
                        float2 x1 = __half22float2(((const __half2*)&xv)[1]);
                        float2 x2 = __half22float2(((const __half2*)&xv)[2]);
                        float2 x3 = __half22float2(((const __half2*)&xv)[3]);
                        const float4* p0 = (const float4*)(wp) + cch*64 + lane*2;
                        const float4* p1 = (const float4*)(wp + NHID) + cch*64 + lane*2;
                        float4 wA = p0[0], wB = p0[1];
                        float4 wC = p1[0], wD = p1[1];
                        a0 += wA.x*x0.x + wA.y*x0.y + wA.z*x1.x + wA.w*x1.y
                            + wB.x*x2.x + wB.y*x2.y + wB.z*x3.x + wB.w*x3.y;
                        a1 += wC.x*x0.x + wC.y*x0.y + wC.z*x1.x + wC.w*x1.y
                            + wD.x*x2.x + wD.y*x2.y + wD.z*x3.x + wD.w*x3.y;
                    }
                    a0 = wredsum(a0); a1 = wredsum(a1);
                    if (lane == 0) {
                        float l0 = a0 + bp[0] + 1.0f;   // P_BIAS on logit 0
                        float l1 = a1 + bp[1];
                        float m  = fmaxf(l0, l1);
                        float e0 = __expf(l0 - m), e1 = __expf(l1 - m);
                        float inv = 1.f / (e0 + e1);
                        dout[OUT_PROBS + t*2 + 0] = e0 * inv;
                        dout[OUT_PROBS + t*2 + 1] = e1 * inv;
                    }
                }
            }
        }

        gbar((unsigned)(p + 1) * NCTA);
    }

    // epilogue: heads for t = 100 (h_3(100) written at phase 103 -> buffer 1)
    if (is_head) {
        const uint4* xs = (const uint4*)(&g_hout[1][3][0]);
        for (int r = wid; r < NST; r += 28) {
            const uint4* wrow = (const uint4*)(g_ws + r*NHID);
            float a = 0.f;
#pragma unroll
            for (int cch = 0; cch < 4; ++cch)
                a += d8hh(wrow[cch*32 + lane], xs[cch*32 + lane]);
            a = wredsum(a);
            if (lane == 0) dout[OUT_STATES + (TSTEPS-1)*NST + r] = a + bs[r];
        }
    }
}

extern "C" void kernel_launch(void* const* d_in, const int* in_sizes, int n_in,
                              void* d_out, int out_size) {
    (void)in_sizes; (void)n_in; (void)out_size;
    const float* z   = (const float*)d_in[0];
    const float* wih = (const float*)d_in[1];
    const float* whh = (const float*)d_in[2];
    const float* bih = (const float*)d_in[3];
    const float* bhh = (const float*)d_in[4];
    const float* ws  = (const float*)d_in[5];
    const float* bs  = (const float*)d_in[6];
    const float* wp  = (const float*)d_in[7];
    const float* bp  = (const float*)d_in[8];
    float* out = (float*)d_out;

    k_prep<<<NROWS, 256>>>(wih, whh);
    k_init<<<256, 256>>>(bih, bhh, ws, out);
    k_lstm<<<NCTA, NTHREADS>>>(z, bs, wp, bp, out);
}

// round 3
// speedup vs baseline: 2.9868x; 1.1684x over previous
#include <cuda_runtime.h>
#include <cuda_fp16.h>
#include <math.h>

#define NHID   1024
#define NLAY   4
#define NST    64
#define TSTEPS 101
#define NUNITS (NLAY*NHID)            // 4096
#define ROWLEN 2048                   // packed row: [Whh(1024) | Wih(1024)]
#define NROWS  (NUNITS*4)             // 16384 gate rows
#define NPHASE (TSTEPS + NLAY - 1)    // 104 wavefront phases
#define NCTA     148
#define NWORK    147
#define NTHREADS 896                  // 28 warps
#define RES_LO 7                      // smem-resident warps [RES_LO, RES_HI]
#define RES_HI 19                     // 13 warps x 16 KB = 208 KB resident
#define S_W_HALFS (13*4*ROWLEN)       // 106496 halfs = 212992 B
#define S_X_OFF   S_W_HALFS           // x region: [h3|h2|h1|h0|z/0] = 5120 halfs
#define SMEM_TOTAL (S_W_HALFS*2 + 5120*2)   // 223232 bytes

#define OUT_STATES 0
#define OUT_PROBS  (TSTEPS*NST)              // 6464
#define OUT_SAMP   (OUT_PROBS + TSTEPS*2)    // 6666

// ---- persistent device state (no allocation allowed) ----
__device__ __align__(128) __half g_wpack[(size_t)NROWS * ROWLEN];  // 64 MB packed fp16 weights
__device__ float  g_bias[NLAY*4*NHID];                             // bih + bhh
__device__ __align__(16) __half g_ws[NST*NHID];                    // fp16 state head
__device__ __align__(16) __half g_hout[2][NLAY][NHID];             // double-buffered hidden (fp16)
__device__ unsigned g_arrive;                                      // monotonic barrier counter

// ---- prep: pack [Whh|Wih] per (unit,gate) row, fp32->fp16 ----
__global__ void k_prep(const float* __restrict__ wih, const float* __restrict__ whh) {
    int row = blockIdx.x;                 // 0..16383 == u*4+g
    int u = row >> 2, g = row & 3;
    int l = u >> 10, j = u & 1023;
    size_t src = ((size_t)l*4096 + g*1024 + j) * 1024;
    __half* dst = g_wpack + (size_t)row * ROWLEN;
    int k = threadIdx.x * 4;              // 256 threads x 4 = 1024
    float4 hv = *(const float4*)(whh + src + k);
    __half2* d0 = (__half2*)(dst + k);
    d0[0] = __floats2half2_rn(hv.x, hv.y);
    d0[1] = __floats2half2_rn(hv.z, hv.w);
    float4 iv = *(const float4*)(wih + src + k);
    __half2* d1 = (__half2*)(dst + 1024 + k);
    d1[0] = __floats2half2_rn(iv.x, iv.y);
    d1[1] = __floats2half2_rn(iv.z, iv.w);
}

// ---- init ----
__global__ void k_init(const float* __restrict__ bih, const float* __restrict__ bhh,
                       const float* __restrict__ ws, float* __restrict__ dout) {
    int i = blockIdx.x * blockDim.x + threadIdx.x;     // 65536 threads
    if (i < NLAY*4*NHID)  g_bias[i] = bih[i] + bhh[i];
    if (i < NST*NHID)     g_ws[i] = __float2half_rn(ws[i]);
    if (i < 2*NLAY*NHID)  ((__half*)g_hout)[i] = __float2half(0.f);
    if (i < TSTEPS)       dout[OUT_SAMP + i] = (i == TSTEPS-1) ? 1.f : 0.f;
    if (i == 0) {
        g_arrive = 0;
        dout[OUT_PROBS + 2*(TSTEPS-1) + 0] = 0.f;   // forced last-step probs
        dout[OUT_PROBS + 2*(TSTEPS-1) + 1] = 1.f;
    }
}

// ---- helpers ----
// 8-term fp16 dot (HFMA2 chain), folded to f32. Window depth 4 half2 ops.
__device__ __forceinline__ float hdot8(uint4 w, uint4 x) {
    __half2 a = __hmul2(((const __half2*)&w)[0], ((const __half2*)&x)[0]);
    a = __hfma2(((const __half2*)&w)[1], ((const __half2*)&x)[1], a);
    a = __hfma2(((const __half2*)&w)[2], ((const __half2*)&x)[2], a);
    a = __hfma2(((const __half2*)&w)[3], ((const __half2*)&x)[3], a);
    float2 f = __half22float2(a);
    return f.x + f.y;
}

__device__ __forceinline__ float wredsum(float v) {
    v += __shfl_xor_sync(0xffffffffu, v, 16);
    v += __shfl_xor_sync(0xffffffffu, v, 8);
    v += __shfl_xor_sync(0xffffffffu, v, 4);
    v += __shfl_xor_sync(0xffffffffu, v, 2);
    v += __shfl_xor_sync(0xffffffffu, v, 1);
    return v;
}

__device__ __forceinline__ float sigf(float x) { return 1.f / (1.f + __expf(-x)); }

// 4 gate-row dots over NC*256 elements; weights from smem (RES) or L2 (!RES)
template <int NC, bool RES>
__device__ __forceinline__ void gatedot(const uint4* __restrict__ wsrc,
                                        const uint4* __restrict__ xs, int lane,
                                        float& a0, float& a1, float& a2, float& a3) {
#pragma unroll
    for (int c = 0; c < NC; ++c) {
        uint4 xv = xs[c*32 + lane];
        uint4 w0, w1, w2, w3;
        if (RES) {
            w0 = wsrc[c*32 + lane];
            w1 = wsrc[256 + c*32 + lane];
            w2 = wsrc[512 + c*32 + lane];
            w3 = wsrc[768 + c*32 + lane];
        } else {
            w0 = __ldg(wsrc + c*32 + lane);
            w1 = __ldg(wsrc + 256 + c*32 + lane);
            w2 = __ldg(wsrc + 512 + c*32 + lane);
            w3 = __ldg(wsrc + 768 + c*32 + lane);
        }
        a0 += hdot8(w0, xv);
        a1 += hdot8(w1, xv);
        a2 += hdot8(w2, xv);
        a3 += hdot8(w3, xv);
    }
}

// grid barrier: monotonic counter, release-add + acquire-poll
__device__ __forceinline__ void gbar(unsigned target) {
    __syncthreads();
    if (threadIdx.x == 0) {
        asm volatile("red.release.gpu.global.add.u32 [%0], %1;"
                     :: "l"(&g_arrive), "r"(1u) : "memory");
        unsigned v;
        do {
            asm volatile("ld.acquire.gpu.global.u32 %0, [%1];"
                         : "=r"(v) : "l"(&g_arrive) : "memory");
        } while (v < target);
    }
    __syncthreads();
}

// ---- main persistent kernel: 104 wavefront phases ----
__global__ void __launch_bounds__(NTHREADS, 1) k_lstm(
    const float* __restrict__ z,
    const float* __restrict__ bs,
    const float* __restrict__ wp,
    const float* __restrict__ bp,
    float* __restrict__ dout)
{
    extern __shared__ __align__(16) char smem[];
    __half* s_w = (__half*)smem;                 // resident weights: 13 x 8192 halfs
    __half* s_x = (__half*)smem + S_X_OFF;       // [h3|h2|h1|h0|z/0] : 5120 halfs

    const int tid  = threadIdx.x;
    const int bid  = blockIdx.x;
    const int wid  = tid >> 5;
    const int lane = tid & 31;
    const bool is_head = (bid == NCTA - 1);

    int u = is_head ? -1 : (wid * NWORK + bid);  // permanent unit ownership
    if (u >= NUNITS) u = -1;
    const int l = (u >= 0) ? (u >> 10) : 0;
    const int j = (u >= 0) ? (u & 1023) : 0;
    const __half* wr = g_wpack + (size_t)((u >= 0) ? u : 0) * 4 * ROWLEN;
    const bool resident = (u >= 0) && (wid >= RES_LO) && (wid <= RES_HI);

    // one-time copy of resident warps' weights into smem (warp-private)
    if (resident) {
        const uint4* src = (const uint4*)wr;
        uint4* dst = (uint4*)(s_w + (size_t)(wid - RES_LO) * 4 * ROWLEN);
#pragma unroll 4
        for (int i = lane; i < 1024; i += 32) dst[i] = src[i];
    }
    const uint4* wsrc = resident
        ? (const uint4*)(s_w + (size_t)(wid - RES_LO) * 4 * ROWLEN)
        : (const uint4*)wr;
    __syncthreads();

    float c = 0.f;                               // cell state lives in registers

    for (int p = 0; p < NPHASE; ++p) {
        const int rb = (p & 1) ^ 1;              // previous-phase buffer
        const int wbuf = p & 1;

        // stage x: s_x = [h3|h2|h1|h0] (+ z at p==0, zeros written at p==1)
        {
            const int n2 = (p <= 1) ? 1280 : 1024;      // uint2 elements (4 halfs)
            for (int i2 = tid; i2 < n2; i2 += NTHREADS) {
                int chunk = i2 >> 8, k2 = i2 & 255;
                uint2 v;
                if (chunk < 4) {
                    v = ((const uint2*)&g_hout[rb][3 - chunk][0])[k2];
                } else if (p == 0) {
                    float4 zz = ((const float4*)z)[k2];
                    __half2 h0 = __floats2half2_rn(zz.x, zz.y);
                    __half2 h1 = __floats2half2_rn(zz.z, zz.w);
                    v.x = *(unsigned*)&h0; v.y = *(unsigned*)&h1;
                } else {
                    v.x = 0u; v.y = 0u;
                }
                ((uint2*)s_x)[i2] = v;
            }
        }
        __syncthreads();

        if (u >= 0) {
            const int t = p - l;
            if (t >= 0 && t < TSTEPS) {
                float a0 = 0.f, a1 = 0.f, a2 = 0.f, a3 = 0.f;
                const uint4* xs = (const uint4*)(s_x + (3 - l) * 1024);
                if (l == 0 && p > 0) {           // x==0 for t>0: Whh half only
                    if (resident) gatedot<4, true >(wsrc, xs, lane, a0, a1, a2, a3);
                    else          gatedot<4, false>(wsrc, xs, lane, a0, a1, a2, a3);
                } else {
                    if (resident) gatedot<8, true >(wsrc, xs, lane, a0, a1, a2, a3);
                    else          gatedot<8, false>(wsrc, xs, lane, a0, a1, a2, a3);
                }
                a0 = wredsum(a0); a1 = wredsum(a1);
                a2 = wredsum(a2); a3 = wredsum(a3);
                if (lane == 0) {
                    const float* bl = g_bias + l*4096 + j;
                    float gi = a0 + bl[0];
                    float gf = a1 + bl[1024];
                    float gg = a2 + bl[2048];
                    float go = a3 + bl[3072];
                    c = sigf(gf) * c + sigf(gi) * tanhf(gg);
                    float hn = sigf(go) * tanhf(c);
                    g_hout[wbuf][l][j] = __float2half_rn(hn);
                }
                c = __shfl_sync(0xffffffffu, c, 0);   // keep c coherent across lanes
            }
        } else if (is_head && p >= 4) {
            // heads for t = p-4; h_3(t) == s_x[0..1024)
            const int t = p - 4;
            const uint4* xs = (const uint4*)s_x;
            for (int r = wid; r < NST + 2; r += 28) {
                if (r < NST) {
                    const uint4* wrow = (const uint4*)(g_ws + r*NHID);
                    float a = 0.f;
#pragma unroll
                    for (int cch = 0; cch < 4; ++cch)
                        a += hdot8(__ldg(wrow + cch*32 + lane), xs[cch*32 + lane]);
                    a = wredsum(a);
                    if (lane == 0) dout[OUT_STATES + t*NST + r] = a + bs[r];
                } else if (r == NST) {
                    float a0 = 0.f, a1 = 0.f;
#pragma unroll
                    for (int cch = 0; cch < 4; ++cch) {
                        uint4 xv = xs[cch*32 + lane];
                        float2 x0 = __half22float2(((const __half2*)&xv)[0]);
                        float2 x1 = __half22float2(((const __half2*)&xv)[1]);
                        float2 x2 = __half22float2(((const __half2*)&xv)[2]);
                        float2 x3 = __half22float2(((const __half2*)&xv)[3]);
                        const float4* p0 = (const float4*)(wp) + cch*64 + lane*2;
                        const float4* p1 = (const float4*)(wp + NHID) + cch*64 + lane*2;
                        float4 wA = p0[0], wB = p0[1];
                        float4 wC = p1[0], wD = p1[1];
                        a0 += wA.x*x0.x + wA.y*x0.y + wA.z*x1.x + wA.w*x1.y
                            + wB.x*x2.x + wB.y*x2.y + wB.z*x3.x + wB.w*x3.y;
                        a1 += wC.x*x0.x + wC.y*x0.y + wC.z*x1.x + wC.w*x1.y
                            + wD.x*x2.x + wD.y*x2.y + wD.z*x3.x + wD.w*x3.y;
                    }
                    a0 = wredsum(a0); a1 = wredsum(a1);
                    if (lane == 0) {
                        float l0 = a0 + bp[0] + 1.0f;   // P_BIAS on logit 0
                        float l1 = a1 + bp[1];
                        float m  = fmaxf(l0, l1);
                        float e0 = __expf(l0 - m), e1 = __expf(l1 - m);
                        float inv = 1.f / (e0 + e1);
                        dout[OUT_PROBS + t*2 + 0] = e0 * inv;
                        dout[OUT_PROBS + t*2 + 1] = e1 * inv;
                    }
                }
            }
        }

        gbar((unsigned)(p + 1) * NCTA);
    }

    // epilogue: heads for t = 100 (h_3(100) written at phase 103 -> buffer 1)
    if (is_head) {
        const uint4* xs = (const uint4*)(&g_hout[1][3][0]);
        for (int r = wid; r < NST; r += 28) {
            const uint4* wrow = (const uint4*)(g_ws + r*NHID);
            float a = 0.f;
#pragma unroll
            for (int cch = 0; cch < 4; ++cch)
                a += hdot8(__ldg(wrow + cch*32 + lane), xs[cch*32 + lane]);
            a = wredsum(a);
            if (lane == 0) dout[OUT_STATES + (TSTEPS-1)*NST + r] = a + bs[r];
        }
    }
}

extern "C" void kernel_launch(void* const* d_in, const int* in_sizes, int n_in,
                              void* d_out, int out_size) {
    (void)in_sizes; (void)n_in; (void)out_size;
    const float* z   = (const float*)d_in[0];
    const float* wih = (const float*)d_in[1];
    const float* whh = (const float*)d_in[2];
    const float* bih = (const float*)d_in[3];
    const float* bhh = (const float*)d_in[4];
    const float* ws  = (const float*)d_in[5];
    const float* bs  = (const float*)d_in[6];
    const float* wp  = (const float*)d_in[7];
    const float* bp  = (const float*)d_in[8];
    float* out = (float*)d_out;

    cudaFuncSetAttribute(k_lstm, cudaFuncAttributeMaxDynamicSharedMemorySize, SMEM_TOTAL);

    k_prep<<<NROWS, 256>>>(wih, whh);
    k_init<<<256, 256>>>(bih, bhh, ws, out);
    k_lstm<<<NCTA, NTHREADS, SMEM_TOTAL>>>(z, bs, wp, bp, out);
}

// round 4
// speedup vs baseline: 3.7532x; 1.2566x over previous
#include <cuda_runtime.h>
#include <cuda_fp16.h>
#include <math.h>

#define NHID   1024
#define NLAY   4
#define NST    64
#define TSTEPS 101
#define NUNITS (NLAY*NHID)            // 4096
#define ROWLEN 2048                   // packed row: [Whh(1024) | Wih(1024)]
#define NROWS  (NUNITS*4)             // 16384 gate rows
#define NPHASE (TSTEPS + NLAY - 1)    // 104 wavefront phases
#define NCTA     148
#define NWORK    147
#define NTHREADS 896                  // 28 warps
#define RES_LO 7                      // full-resident warps [7,19]
#define RES_HI 19
// smem: warp0 Whh-half (4096 halfs) + 13 full rows (8192 halfs each) + x buffer
#define S_W_HALFS (4096 + 13*4*ROWLEN)       // 110592 halfs = 221184 B
#define S_X_OFF   S_W_HALFS                  // x region: [h3|h2|h1|h0|z/0] = 5120 halfs
#define SMEM_TOTAL ((S_W_HALFS + 5120) * 2)  // 231424 bytes

#define OUT_STATES 0
#define OUT_PROBS  (TSTEPS*NST)              // 6464
#define OUT_SAMP   (OUT_PROBS + TSTEPS*2)    // 6666

#define H2(v,k) (((const __half2*)&(v))[k])

// ---- persistent device state (no allocation allowed) ----
__device__ __align__(128) __half g_wpack[(size_t)NROWS * ROWLEN];  // 64 MB packed fp16 weights
__device__ float  g_bias[NLAY*4*NHID];                             // bih + bhh
__device__ __align__(16) __half g_ws[NST*NHID];                    // fp16 state head
__device__ __align__(16) __half g_hout[2][NLAY][NHID];             // double-buffered hidden (fp16)
__device__ unsigned g_arrive;                                      // monotonic barrier counter

// ---- prep: pack [Whh|Wih] per (unit,gate) row, fp32->fp16 ----
__global__ void k_prep(const float* __restrict__ wih, const float* __restrict__ whh) {
    int row = blockIdx.x;                 // 0..16383 == u*4+g
    int u = row >> 2, g = row & 3;
    int l = u >> 10, j = u & 1023;
    size_t src = ((size_t)l*4096 + g*1024 + j) * 1024;
    __half* dst = g_wpack + (size_t)row * ROWLEN;
    int k = threadIdx.x * 4;              // 256 threads x 4 = 1024
    float4 hv = *(const float4*)(whh + src + k);
    __half2* d0 = (__half2*)(dst + k);
    d0[0] = __floats2half2_rn(hv.x, hv.y);
    d0[1] = __floats2half2_rn(hv.z, hv.w);
    float4 iv = *(const float4*)(wih + src + k);
    __half2* d1 = (__half2*)(dst + 1024 + k);
    d1[0] = __floats2half2_rn(iv.x, iv.y);
    d1[1] = __floats2half2_rn(iv.z, iv.w);
}

// ---- init ----
__global__ void k_init(const float* __restrict__ bih, const float* __restrict__ bhh,
                       const float* __restrict__ ws, float* __restrict__ dout) {
    int i = blockIdx.x * blockDim.x + threadIdx.x;     // 65536 threads
    if (i < NLAY*4*NHID)  g_bias[i] = bih[i] + bhh[i];
    if (i < NST*NHID)     g_ws[i] = __float2half_rn(ws[i]);
    if (i < 2*NLAY*NHID)  ((__half*)g_hout)[i] = __float2half(0.f);
    if (i < TSTEPS)       dout[OUT_SAMP + i] = (i == TSTEPS-1) ? 1.f : 0.f;
    if (i == 0) {
        g_arrive = 0;
        dout[OUT_PROBS + 2*(TSTEPS-1) + 0] = 0.f;   // forced last-step probs
        dout[OUT_PROBS + 2*(TSTEPS-1) + 1] = 1.f;
    }
}

// ---- helpers ----
__device__ __forceinline__ float hdot8(uint4 w, uint4 x) {
    __half2 a = __hmul2(H2(w,0), H2(x,0));
    a = __hfma2(H2(w,1), H2(x,1), a);
    a = __hfma2(H2(w,2), H2(x,2), a);
    a = __hfma2(H2(w,3), H2(x,3), a);
    return __low2float(a) + __high2float(a);
}

__device__ __forceinline__ float wredsum(float v) {
    v += __shfl_xor_sync(0xffffffffu, v, 16);
    v += __shfl_xor_sync(0xffffffffu, v, 8);
    v += __shfl_xor_sync(0xffffffffu, v, 4);
    v += __shfl_xor_sync(0xffffffffu, v, 2);
    v += __shfl_xor_sync(0xffffffffu, v, 1);
    return v;
}

__device__ __forceinline__ float sigf(float x) {
    return __fdividef(1.f, 1.f + __expf(-x));
}
__device__ __forceinline__ float tanhfast(float x) {
    return 2.f * sigf(2.f * x) - 1.f;
}

// 4 gate-row dots over NPAIR*2 chunks (16-term fp16 windows).
// GS = gate stride in uint4. PF: chunk-0 weights come prefetched in pw[4].
template <int NPAIR, int GS, bool RES, bool PF>
__device__ __forceinline__ void gatedot4(const uint4* __restrict__ w,
                                         const uint4* __restrict__ xs, int lane,
                                         const uint4* pw, float* a)
{
#pragma unroll
    for (int cp = 0; cp < NPAIR; ++cp) {
        uint4 xa = xs[cp*64 + lane];
        uint4 xb = xs[cp*64 + 32 + lane];
#pragma unroll
        for (int g = 0; g < 4; ++g) {
            uint4 wa;
            if (PF && cp == 0) wa = pw[g];
            else wa = RES ? w[g*GS + cp*64 + lane] : __ldg(w + g*GS + cp*64 + lane);
            uint4 wb = RES ? w[g*GS + cp*64 + 32 + lane]
                           : __ldg(w + g*GS + cp*64 + 32 + lane);
            __half2 h = __hmul2(H2(wa,0), H2(xa,0));
            h = __hfma2(H2(wa,1), H2(xa,1), h);
            h = __hfma2(H2(wa,2), H2(xa,2), h);
            h = __hfma2(H2(wa,3), H2(xa,3), h);
            h = __hfma2(H2(wb,0), H2(xb,0), h);
            h = __hfma2(H2(wb,1), H2(xb,1), h);
            h = __hfma2(H2(wb,2), H2(xb,2), h);
            h = __hfma2(H2(wb,3), H2(xb,3), h);
            a[g] += __low2float(h) + __high2float(h);
        }
    }
}

// ---- main persistent kernel: 104 wavefront phases ----
__global__ void __launch_bounds__(NTHREADS, 1) k_lstm(
    const float* __restrict__ z,
    const float* __restrict__ bs,
    const float* __restrict__ wp,
    const float* __restrict__ bp,
    float* __restrict__ dout)
{
    extern __shared__ __align__(16) char smem[];
    __half* s_w = (__half*)smem;
    __half* s_x = (__half*)smem + S_X_OFF;   // [h3|h2|h1|h0|z/0]

    const int tid  = threadIdx.x;
    const int bid  = blockIdx.x;
    const int wid  = tid >> 5;
    const int lane = tid & 31;
    const bool is_head = (bid == NCTA - 1);

    int u = is_head ? -1 : (wid * NWORK + bid);      // permanent unit ownership
    if (u >= NUNITS) u = -1;
    const int l = (u >= 0) ? (u >> 10) : 0;
    const int j = (u >= 0) ? (u & 1023) : 0;
    const uint4* wr4 = (const uint4*)(g_wpack + (size_t)((u >= 0) ? u : 0) * 4 * ROWLEN);
    const bool res_half = (u >= 0) && (wid == 0);              // layer-0, Whh half in smem
    const bool res_full = (u >= 0) && (wid >= RES_LO) && (wid <= RES_HI);

    // one-time smem weight copies (warp-private)
    if (res_half) {
        uint4* dst = (uint4*)s_w;
#pragma unroll
        for (int g = 0; g < 4; ++g)
            for (int i = lane; i < 128; i += 32) dst[g*128 + i] = wr4[g*256 + i];
    } else if (res_full) {
        uint4* dst = (uint4*)s_w + 512 + (wid - RES_LO) * 1024;
#pragma unroll 4
        for (int i = lane; i < 1024; i += 32) dst[i] = wr4[i];
    }
    const uint4* wsm4 = res_half ? (const uint4*)s_w
                       : res_full ? (const uint4*)s_w + 512 + (wid - RES_LO) * 1024
                       : wr4;
    __syncthreads();

    // phase-invariant per-warp state
    float b0 = 0.f, b1 = 0.f, b2 = 0.f, b3 = 0.f;
    if (u >= 0) {
        const float* bl = g_bias + l*4096 + j;
        b0 = bl[0]; b1 = bl[1024]; b2 = bl[2048]; b3 = bl[3072];
    }
    float c = 0.f;

    // prefetch chunk-0 weights for the steady-state path
    uint4 pw[4];
    auto load_pw = [&]() {
        if (u >= 0) {
            if (res_half) {
#pragma unroll
                for (int g = 0; g < 4; ++g) pw[g] = wsm4[g*128 + lane];
            } else if (res_full) {
#pragma unroll
                for (int g = 0; g < 4; ++g) pw[g] = wsm4[g*256 + lane];
            } else {
#pragma unroll
                for (int g = 0; g < 4; ++g) pw[g] = __ldg(wr4 + g*256 + lane);
            }
        }
    };
    load_pw();

    for (int p = 0; p < NPHASE; ++p) {
        const int rb = (p & 1) ^ 1;
        const int wbuf = p & 1;

        // stage x: one uint4 per thread; [h3|h2|h1|h0], z/zeros at p<=1
        if (tid < 512) {
            int chunk = tid >> 7, k = tid & 127;
            ((uint4*)s_x)[tid] = ((const uint4*)&g_hout[rb][3 - chunk][0])[k];
        } else if (p <= 1 && tid < 640) {
            int k = tid - 512;
            uint4 v;
            if (p == 0) {
                float4 z0 = ((const float4*)z)[k*2];
                float4 z1 = ((const float4*)z)[k*2 + 1];
                __half2 h0 = __floats2half2_rn(z0.x, z0.y);
                __half2 h1 = __floats2half2_rn(z0.z, z0.w);
                __half2 h2 = __floats2half2_rn(z1.x, z1.y);
                __half2 h3 = __floats2half2_rn(z1.z, z1.w);
                v.x = *(unsigned*)&h0; v.y = *(unsigned*)&h1;
                v.z = *(unsigned*)&h2; v.w = *(unsigned*)&h3;
            } else { v.x = v.y = v.z = v.w = 0u; }
            ((uint4*)s_x)[tid] = v;
        }
        __syncthreads();

        if (u >= 0) {
            const int t = p - l;
            if (t >= 0 && t < TSTEPS) {
                float a[4] = {0.f, 0.f, 0.f, 0.f};
                if (l == 0) {
                    if (t == 0)        // h==0: only Wih * z (global, Wih at +128 uint4)
                        gatedot4<2,256,false,false>(wr4 + 128, (const uint4*)s_x + 512, lane, pw, a);
                    else if (res_half) // Whh half from smem
                        gatedot4<2,128,true,true>(wsm4, (const uint4*)s_x + 384, lane, pw, a);
                    else
                        gatedot4<2,256,false,true>(wr4, (const uint4*)s_x + 384, lane, pw, a);
                } else {
                    const uint4* xs = (const uint4*)s_x + (3 - l) * 128;
                    if (res_full)
                        gatedot4<4,256,true,true>(wsm4, xs, lane, pw, a);
                    else
                        gatedot4<4,256,false,true>(wr4, xs, lane, pw, a);
                }
                float gi = wredsum(a[0]) + b0;
                float gf = wredsum(a[1]) + b1;
                float gg = wredsum(a[2]) + b2;
                float go = wredsum(a[3]) + b3;
                // all lanes compute identically (wredsum is lane-uniform)
                c = sigf(gf) * c + sigf(gi) * tanhfast(gg);
                float hn = sigf(go) * tanhfast(c);
                if (lane == 0) g_hout[wbuf][l][j] = __float2half_rn(hn);
            }
        } else if (is_head && p >= 4) {
            // heads for t = p-4; h_3(t) == s_x[0..1024)
            const int t = p - 4;
            const uint4* xs = (const uint4*)s_x;
            for (int r = wid; r < NST + 2; r += 28) {
                if (r < NST) {
                    const uint4* wrow = (const uint4*)(g_ws + r*NHID);
                    float a = 0.f;
#pragma unroll
                    for (int cch = 0; cch < 4; ++cch)
                        a += hdot8(__ldg(wrow + cch*32 + lane), xs[cch*32 + lane]);
                    a = wredsum(a);
                    if (lane == 0) dout[OUT_STATES + t*NST + r] = a + bs[r];
                } else if (r == NST) {
                    float a0 = 0.f, a1 = 0.f;
#pragma unroll
                    for (int cch = 0; cch < 4; ++cch) {
                        uint4 xv = xs[cch*32 + lane];
                        float2 x0 = __half22float2(H2(xv,0));
                        float2 x1 = __half22float2(H2(xv,1));
                        float2 x2 = __half22float2(H2(xv,2));
                        float2 x3 = __half22float2(H2(xv,3));
                        const float4* p0 = (const float4*)(wp) + cch*64 + lane*2;
                        const float4* p1 = (const float4*)(wp + NHID) + cch*64 + lane*2;
                        float4 wA = p0[0], wB = p0[1];
                        float4 wC = p1[0], wD = p1[1];
                        a0 += wA.x*x0.x + wA.y*x0.y + wA.z*x1.x + wA.w*x1.y
                            + wB.x*x2.x + wB.y*x2.y + wB.z*x3.x + wB.w*x3.y;
                        a1 += wC.x*x0.x + wC.y*x0.y + wC.z*x1.x + wC.w*x1.y
                            + wD.x*x2.x + wD.y*x2.y + wD.z*x3.x + wD.w*x3.y;
                    }
                    a0 = wredsum(a0); a1 = wredsum(a1);
                    if (lane == 0) {
                        float l0v = a0 + bp[0] + 1.0f;   // P_BIAS on logit 0
                        float l1v = a1 + bp[1];
                        float m  = fmaxf(l0v, l1v);
                        float e0 = __expf(l0v - m), e1 = __expf(l1v - m);
                        float inv = 1.f / (e0 + e1);
                        dout[OUT_PROBS + t*2 + 0] = e0 * inv;
                        dout[OUT_PROBS + t*2 + 1] = e1 * inv;
                    }
                }
            }
        }

        // barrier with prefetch overlapped into the wait
        __syncthreads();
        if (tid == 0)
            asm volatile("red.release.gpu.global.add.u32 [%0], %1;"
                         :: "l"(&g_arrive), "r"(1u) : "memory");
        load_pw();                       // phase-invariant; fills during the poll
        if (tid == 0) {
            unsigned target = (unsigned)(p + 1) * NCTA, v;
            do {
                asm volatile("ld.acquire.gpu.global.u32 %0, [%1];"
                             : "=r"(v) : "l"(&g_arrive) : "memory");
            } while (v < target);
        }
        __syncthreads();
    }

    // epilogue: heads for t = 100 (h_3(100) written at phase 103 -> buffer 1)
    if (is_head) {
        const uint4* xs = (const uint4*)(&g_hout[1][3][0]);
        for (int r = wid; r < NST; r += 28) {
            const uint4* wrow = (const uint4*)(g_ws + r*NHID);
            float a = 0.f;
#pragma unroll
            for (int cch = 0; cch < 4; ++cch)
                a += hdot8(__ldg(wrow + cch*32 + lane), xs[cch*32 + lane]);
            a = wredsum(a);
            if (lane == 0) dout[OUT_STATES + (TSTEPS-1)*NST + r] = a + bs[r];
        }
    }
}

extern "C" void kernel_launch(void* const* d_in, const int* in_sizes, int n_in,
                              void* d_out, int out_size) {
    (void)in_sizes; (void)n_in; (void)out_size;
    const float* z   = (const float*)d_in[0];
    const float* wih = (const float*)d_in[1];
    const float* whh = (const float*)d_in[2];
    const float* bih = (const float*)d_in[3];
    const float* bhh = (const float*)d_in[4];
    const float* ws  = (const float*)d_in[5];
    const float* bs  = (const float*)d_in[6];
    const float* wp  = (const float*)d_in[7];
    const float* bp  = (const float*)d_in[8];
    float* out = (float*)d_out;

    cudaFuncSetAttribute(k_lstm, cudaFuncAttributeMaxDynamicSharedMemorySize, SMEM_TOTAL);

    k_prep<<<NROWS, 256>>>(wih, whh);
    k_init<<<256, 256>>>(bih, bhh, ws, out);
    k_lstm<<<NCTA, NTHREADS, SMEM_TOTAL>>>(z, bs, wp, bp, out);
}